// round 10
// baseline (speedup 1.0000x reference)
#include <cuda_runtime.h>

#define NN 512
#define CC 64
#define HH 256
#define EPSF 1e-5f

typedef unsigned long long u64;

// ---------------- packed f32x2 helpers (verified on sm_103a) ----------------
__device__ __forceinline__ u64 pk(float lo, float hi) {
    u64 r; asm("mov.b64 %0,{%1,%2};" : "=l"(r) : "f"(lo), "f"(hi)); return r;
}
__device__ __forceinline__ void unpk(u64 v, float& lo, float& hi) {
    asm("mov.b64 {%0,%1},%2;" : "=f"(lo), "=f"(hi) : "l"(v));
}
__device__ __forceinline__ u64 add2(u64 a, u64 b) {
    u64 r; asm("add.rn.f32x2 %0,%1,%2;" : "=l"(r) : "l"(a), "l"(b)); return r;
}
__device__ __forceinline__ u64 fma2(u64 a, u64 b, u64 c) {
    u64 r; asm("fma.rn.f32x2 %0,%1,%2,%3;" : "=l"(r) : "l"(a), "l"(b), "l"(c)); return r;
}
__device__ __forceinline__ float ex2f(float x) {
    float r; asm("ex2.approx.f32 %0,%1;" : "=f"(r) : "f"(x)); return r;
}
__device__ __forceinline__ float warp_sum(float x) {
#pragma unroll
    for (int off = 16; off > 0; off >>= 1)
        x += __shfl_xor_sync(0xffffffffu, x, off);
    return x;
}

// ---------------- scratch (device globals) ----------------
__device__ float g_RA [NN*HH];
__device__ float g_RB [NN*HH];
__device__ float g_A1M[NN*HH];
__device__ float g_A2P[NN*HH];
__device__ float g_B1P[NN*HH];
__device__ float g_B2M[NN*HH];
__device__ float g_SA2[2][NN];
__device__ float g_SB2[2][NN];
__device__ float g_QA2[2][NN];
__device__ float g_QB2[2][NN];
__device__ float g_DA2[2][NN];
__device__ float g_DB2[2][NN];
__device__ float g_CW2[2], g_CWG2[2], g_CWB2[2];

// ---------------------------------------------------------------------------
// Stage 1: fused GEMM + shift-combine + stats. Grid (64 rowgroups, 2 z, 2 half),
// 128 threads. Block computes rows i0..i0+7 for 128 h-channels directly from
// x and W1 (no intermediate table). Emits RA/RB (+masked parts) and per-row
// stats: S (sum), Q (sum sq), D (sum w2*gamma*r).
// ---------------------------------------------------------------------------
template <int Z>
__device__ __forceinline__ void mm_rows(
    const float xs[10], float w0, float w1, float w2,
    float acc0[8], float acc1[8], float acc2[8])
{
#pragma unroll
    for (int r = 0; r < 8; r++) {
        acc0[r] = fmaf(xs[r + 1], w0, acc0[r]);
        if (Z == 0) {   // A: acc1 = A1 with x[i-1], acc2 = A2 with x[i+1]
            acc1[r] = fmaf(xs[r],     w1, acc1[r]);
            acc2[r] = fmaf(xs[r + 2], w2, acc2[r]);
        } else {        // B: acc1 = B1 with x[j+1], acc2 = B2 with x[j-1]
            acc1[r] = fmaf(xs[r + 2], w1, acc1[r]);
            acc2[r] = fmaf(xs[r],     w2, acc2[r]);
        }
    }
}

__global__ __launch_bounds__(128) void fused_pre_kernel(
    const float* __restrict__ xl, const float* __restrict__ xr,
    const float* __restrict__ W1, const float* __restrict__ b1,
    const float* __restrict__ gamma, const float* __restrict__ beta,
    const float* __restrict__ W2)
{
    __shared__ float xsT[64][12];        // [f][halo row 0..9]
    __shared__ float red[4][8][3];
    __shared__ float redc[4][3];

    const int tid  = threadIdx.x;
    const int i0   = blockIdx.x * 8;
    const int z    = blockIdx.y;
    const int half = blockIdx.z;
    const int h    = half * 128 + tid;
    const int lane = tid & 31, w = tid >> 5;

    const float* X = z ? xr : xl;
    for (int idx = tid; idx < 640; idx += 128) {
        int r = idx / 64, f = idx - r * 64;
        int gi = i0 - 1 + r;
        xsT[f][r] = (gi >= 0 && gi < NN) ? X[gi * CC + f] : 0.f;
    }
    __syncthreads();

    const float* w0p = W1 + ((0 + z) * CC) * HH + h;
    const float* w1p = W1 + ((2 + z) * CC) * HH + h;
    const float* w2p = W1 + ((4 + z) * CC) * HH + h;

    float acc0[8] = {}, acc1[8] = {}, acc2[8] = {};
#pragma unroll 4
    for (int f = 0; f < 64; f++) {
        float w0 = w0p[f * HH], w1 = w1p[f * HH], w2 = w2p[f * HH];
        float4 xa = *reinterpret_cast<const float4*>(&xsT[f][0]);
        float4 xb = *reinterpret_cast<const float4*>(&xsT[f][4]);
        float2 xc = *reinterpret_cast<const float2*>(&xsT[f][8]);
        float xs[10] = {xa.x, xa.y, xa.z, xa.w, xb.x, xb.y, xb.z, xb.w, xc.x, xc.y};
        if (z == 0) mm_rows<0>(xs, w0, w1, w2, acc0, acc1, acc2);
        else        mm_rows<1>(xs, w0, w1, w2, acc0, acc1, acc2);
    }

    const float b1h = (z == 0) ? b1[h] : 0.f;
    const float wg  = W2[h] * gamma[h];

#pragma unroll
    for (int r = 0; r < 8; r++) {
        int i = i0 + r;
        float rr = acc0[r] + acc1[r] + acc2[r] + b1h;
        if (z == 0) {
            g_RA [i * HH + h] = rr;
            g_A1M[i * HH + h] = acc1[r];
            g_A2P[i * HH + h] = acc2[r];
        } else {
            g_RB [i * HH + h] = rr;
            g_B1P[i * HH + h] = acc1[r];
            g_B2M[i * HH + h] = acc2[r];
        }
        float s = warp_sum(rr);
        float q = warp_sum(rr * rr);
        float d = warp_sum(wg * rr);
        if (lane == 0) { red[w][r][0] = s; red[w][r][1] = q; red[w][r][2] = d; }
    }
    // W2 constants (one block pair)
    if (blockIdx.x == 0 && z == 0) {
        float cw  = warp_sum(W2[h]);
        float cwg = warp_sum(wg);
        float cwb = warp_sum(W2[h] * beta[h]);
        if (lane == 0) { redc[w][0] = cw; redc[w][1] = cwg; redc[w][2] = cwb; }
    }
    __syncthreads();
    if (tid < 8) {
        float s = 0.f, q = 0.f, d = 0.f;
#pragma unroll
        for (int k = 0; k < 4; k++) {
            s += red[k][tid][0]; q += red[k][tid][1]; d += red[k][tid][2];
        }
        int i = i0 + tid;
        if (z == 0) { g_SA2[half][i] = s; g_QA2[half][i] = q; g_DA2[half][i] = d; }
        else        { g_SB2[half][i] = s; g_QB2[half][i] = q; g_DB2[half][i] = d; }
    }
    if (blockIdx.x == 0 && z == 0 && tid == 0) {
        float cw = 0.f, cwg = 0.f, cwb = 0.f;
#pragma unroll
        for (int k = 0; k < 4; k++) {
            cw += redc[k][0]; cwg += redc[k][1]; cwb += redc[k][2];
        }
        g_CW2[half] = cw; g_CWG2[half] = cwg; g_CWB2[half] = cwb;
    }
}

// ---------------------------------------------------------------------------
// Stage 2: fused pair kernel. Blocks 0..255: 32x32 tile, R=4 rows/thread.
//   pass1: cross-dot -> variance (sq = QA + QB + 2X).
//   pass2: only the nonlinear CELU residual: u = 2^m' - ln2*m'  (m'=min(h',0));
//          linear part folded into rs*(DA+DB) + nm*CWG + CWB.
// Blocks 256..287: border fixup (full scalar formula).
// ---------------------------------------------------------------------------
#define SA_OFF   0
#define SB_OFF   32768
#define SGB_OFF  66560
#define SW_OFF   68608
#define SSA_OFF  69632
#define SSB_OFF  69760
#define SQA_OFF  69888
#define SQB_OFF  70016
#define SDA_OFF  70144
#define SDB_OFF  70272
#define SMEM_SZ  70400

__global__ __launch_bounds__(256, 3) void pair_fused_kernel(
    const float* __restrict__ gamma, const float* __restrict__ beta,
    const float* __restrict__ W2, const float* __restrict__ b2,
    float* __restrict__ out)
{
    const int t = threadIdx.x;
    const int lane = t & 31, w = t >> 5;

    if (blockIdx.x >= 256) {
        // ================= fixup path =================
        const int fb = blockIdx.x - 256;
#pragma unroll 1
        for (int c = 0; c < 8; c++) {
            const int gw = fb * 8 + w + 256 * c;
            const int side = gw >> 9, pos = gw & 511;
            int i, j;
            if      (side == 0) { i = 0;      j = pos; }
            else if (side == 1) { i = NN - 1; j = pos; }
            else if (side == 2) { i = pos;    j = 0; }
            else                { i = pos;    j = NN - 1; }

            const bool mi0 = (i == 0), mi1 = (i == NN - 1);
            const bool mj0 = (j == 0), mj1 = (j == NN - 1);
            const float4 z4 = make_float4(0.f, 0.f, 0.f, 0.f);

            const float4* RA4 = reinterpret_cast<const float4*>(g_RA)  + i * 64;
            const float4* RB4 = reinterpret_cast<const float4*>(g_RB)  + j * 64;
            const float4* BP4 = reinterpret_cast<const float4*>(g_B1P) + j * 64;
            const float4* BM4 = reinterpret_cast<const float4*>(g_B2M) + j * 64;
            const float4* AP4 = reinterpret_cast<const float4*>(g_A2P) + i * 64;
            const float4* AM4 = reinterpret_cast<const float4*>(g_A1M) + i * 64;

            float s[8], gm[8], bt[8], w2r[8];
#pragma unroll
            for (int half = 0; half < 2; half++) {
                int idx = lane + 32 * half;
                float4 ra = RA4[idx];
                float4 rb = RB4[idx];
                float4 c1 = mi0 ? BP4[idx] : z4;
                float4 c2 = mi1 ? BM4[idx] : z4;
                float4 c3 = mj0 ? AP4[idx] : z4;
                float4 c4 = mj1 ? AM4[idx] : z4;
                int o = 4 * half;
                s[o + 0] = ra.x + rb.x - c1.x - c2.x - c3.x - c4.x;
                s[o + 1] = ra.y + rb.y - c1.y - c2.y - c3.y - c4.y;
                s[o + 2] = ra.z + rb.z - c1.z - c2.z - c3.z - c4.z;
                s[o + 3] = ra.w + rb.w - c1.w - c2.w - c3.w - c4.w;
                float4 gv = reinterpret_cast<const float4*>(gamma)[idx];
                float4 bv = reinterpret_cast<const float4*>(beta )[idx];
                float4 wv = reinterpret_cast<const float4*>(W2   )[idx];
                gm[o] = gv.x; gm[o+1] = gv.y; gm[o+2] = gv.z; gm[o+3] = gv.w;
                bt[o] = bv.x; bt[o+1] = bv.y; bt[o+2] = bv.z; bt[o+3] = bv.w;
                w2r[o] = wv.x; w2r[o+1] = wv.y; w2r[o+2] = wv.z; w2r[o+3] = wv.w;
            }

            float sum = ((s[0] + s[1]) + (s[2] + s[3])) + ((s[4] + s[5]) + (s[6] + s[7]));
            float sq  = fmaf(s[0], s[0], s[1] * s[1]);
            sq = fmaf(s[2], s[2], fmaf(s[3], s[3], sq));
            sq = fmaf(s[4], s[4], sq);
            sq = fmaf(s[5], s[5], sq);
            sq = fmaf(s[6], s[6], fmaf(s[7], s[7], sq));
            sum = warp_sum(sum);
            sq  = warp_sum(sq);

            float mu  = sum * (1.f / 256.f);
            float var = fmaf(sq, 1.f / 256.f, -mu * mu);
            float rs  = rsqrtf(var + EPSF);
            float nm  = -mu * rs;
            float acc = 0.f;
#pragma unroll
            for (int k = 0; k < 8; k++) {
                float hn = fmaf(fmaf(s[k], rs, nm), gm[k], bt[k]);
                float e  = __expf(fminf(hn, 0.f)) - 1.f;
                float v  = fmaxf(hn, 0.f) + e;
                acc = fmaf(v, w2r[k], acc);
            }
            acc = warp_sum(acc);
            if (lane == 0) out[i * NN + j] = acc + b2[0];
        }
        return;
    }

    // ================= main tile path =================
    extern __shared__ __align__(16) char smem_raw[];
    u64 (*sA)[128] = reinterpret_cast<u64(*)[128]>(smem_raw + SA_OFF);
    u64 (*sB)[33]  = reinterpret_cast<u64(*)[33]>(smem_raw + SB_OFF);
    u64 (*sGB)[2]  = reinterpret_cast<u64(*)[2]>(smem_raw + SGB_OFF);
    u64* sW  = reinterpret_cast<u64*>(smem_raw + SW_OFF);
    float* sSA = reinterpret_cast<float*>(smem_raw + SSA_OFF);
    float* sSB = reinterpret_cast<float*>(smem_raw + SSB_OFF);
    float* sQA = reinterpret_cast<float*>(smem_raw + SQA_OFF);
    float* sQB = reinterpret_cast<float*>(smem_raw + SQB_OFF);
    float* sDA = reinterpret_cast<float*>(smem_raw + SDA_OFF);
    float* sDB = reinterpret_cast<float*>(smem_raw + SDB_OFF);

    const int i0 = (blockIdx.x >> 4) * 32, j0 = (blockIdx.x & 15) * 32;
    const float L2E  = 1.4426950408889634f;
    const float MLN2 = -0.6931471805599453f;

    {
        const u64* gA = reinterpret_cast<const u64*>(g_RA) + i0 * 128;
#pragma unroll
        for (int k = 0; k < 16; k++) {
            int idx = t + 256 * k;
            sA[idx >> 7][idx & 127] = gA[idx];
        }
    }
    {
        const u64* gB = reinterpret_cast<const u64*>(g_RB) + j0 * 128;
        int j = t >> 3, part = t & 7;
#pragma unroll
        for (int k = 0; k < 16; k++) {
            int c2 = part + 8 * k;
            sB[c2][j] = gB[j * 128 + c2];
        }
    }
    if (t < 128) {
        float2 gv = reinterpret_cast<const float2*>(gamma)[t];
        float2 bv = reinterpret_cast<const float2*>(beta)[t];
        float2 wv = reinterpret_cast<const float2*>(W2)[t];
        sGB[t][0] = pk(gv.x * L2E, gv.y * L2E);
        sGB[t][1] = pk(bv.x * L2E, bv.y * L2E);
        sW [t]    = pk(wv.x, wv.y);
        if (t < 32)            sDA[t]      = g_DA2[0][i0 + t] + g_DA2[1][i0 + t];
        else if (t < 64)       sDB[t - 32] = g_DB2[0][j0 + t - 32] + g_DB2[1][j0 + t - 32];
    } else if (t < 160) {
        sSA[t - 128] = g_SA2[0][i0 + t - 128] + g_SA2[1][i0 + t - 128];
    } else if (t < 192) {
        sSB[t - 160] = g_SB2[0][j0 + t - 160] + g_SB2[1][j0 + t - 160];
    } else if (t < 224) {
        sQA[t - 192] = g_QA2[0][i0 + t - 192] + g_QA2[1][i0 + t - 192];
    } else {
        sQB[t - 224] = g_QB2[0][j0 + t - 224] + g_QB2[1][j0 + t - 224];
    }
    const float CW  = g_CW2[0] + g_CW2[1];
    const float CWG = g_CWG2[0] + g_CWG2[1];
    const float CWB = g_CWB2[0] + g_CWB2[1];
    const float CADD = b2[0] - CW + CWB;
    __syncthreads();

    const int r0 = 4 * w;

    // ---- pass 1: cross-dot X[r] = sum_c RA*RB (packed, pipelined) ----
    u64 xd[4] = {0, 0, 0, 0};
    {
        u64 bv = sB[0][lane];
#pragma unroll 8
        for (int c2 = 0; c2 < 128; c2++) {
            u64 bvn = sB[(c2 + 1) & 127][lane];
#pragma unroll
            for (int r = 0; r < 4; r++)
                xd[r] = fma2(sA[r0 + r][c2], bv, xd[r]);
            bv = bvn;
        }
    }
    u64 rs2[4], nm2[4];
    float rsS[4], nmS[4];
#pragma unroll
    for (int r = 0; r < 4; r++) {
        float xl_, xh_; unpk(xd[r], xl_, xh_);
        float sq  = sQA[r0 + r] + sQB[lane] + 2.f * (xl_ + xh_);
        float sum = sSA[r0 + r] + sSB[lane];
        float mu  = sum * (1.f / 256.f);
        float var = fmaf(sq, 1.f / 256.f, -mu * mu);
        float rs  = rsqrtf(var + EPSF);
        float nm  = -mu * rs;
        rsS[r] = rs; nmS[r] = nm;
        rs2[r] = pk(rs, rs);
        nm2[r] = pk(nm, nm);
    }

    // ---- pass 2: CELU residual u = 2^m' - ln2*m', accumulate w2*u ----
    u64 ae[4] = {0, 0, 0, 0};
    {
        u64 bv = sB[0][lane];
        ulonglong2 gb = *reinterpret_cast<const ulonglong2*>(sGB[0]);
        u64 wv = sW[0];
#pragma unroll 4
        for (int c2 = 0; c2 < 128; c2++) {
            const int cn = (c2 + 1) & 127;
            u64 bvn = sB[cn][lane];
            ulonglong2 gbn = *reinterpret_cast<const ulonglong2*>(sGB[cn]);
            u64 wvn = sW[cn];
#pragma unroll
            for (int r = 0; r < 4; r++) {
                u64 s = add2(sA[r0 + r][c2], bv);
                u64 h = fma2(fma2(s, rs2[r], nm2[r]), gb.x, gb.y);
                float hl, hh; unpk(h, hl, hh);
                float ml = fminf(hl, 0.f);
                float mh = fminf(hh, 0.f);
                float ul = fmaf(MLN2, ml, ex2f(ml));
                float uh = fmaf(MLN2, mh, ex2f(mh));
                ae[r] = fma2(pk(ul, uh), wv, ae[r]);
            }
            bv = bvn; gb = gbn; wv = wvn;
        }
    }

    const int gj = j0 + lane;
    const bool jint = (gj != 0) && (gj != NN - 1);
#pragma unroll
    for (int r = 0; r < 4; r++) {
        int gi = i0 + r0 + r;
        if (jint && gi != 0 && gi != NN - 1) {
            float dd = sDA[r0 + r] + sDB[lane];
            float lin = fmaf(rsS[r], dd, nmS[r] * CWG);
            float a, b; unpk(ae[r], a, b);
            out[gi * NN + gj] = lin + (a + b) + CADD;
        }
    }
}

// ---------------------------------------------------------------------------
extern "C" void kernel_launch(void* const* d_in, const int* in_sizes, int n_in,
                              void* d_out, int out_size)
{
    const float* xl    = (const float*)d_in[0];
    const float* xr    = (const float*)d_in[1];
    const float* W1    = (const float*)d_in[2];
    const float* b1    = (const float*)d_in[3];
    const float* gamma = (const float*)d_in[4];
    const float* beta  = (const float*)d_in[5];
    const float* W2    = (const float*)d_in[6];
    const float* b2    = (const float*)d_in[7];
    float* out = (float*)d_out;

    static bool attr_set = false;
    if (!attr_set) {
        cudaFuncSetAttribute(pair_fused_kernel,
                             cudaFuncAttributeMaxDynamicSharedMemorySize, SMEM_SZ);
        attr_set = true;
    }

    dim3 gpre(64, 2, 2);
    fused_pre_kernel<<<gpre, 128>>>(xl, xr, W1, b1, gamma, beta, W2);
    pair_fused_kernel<<<256 + 32, 256, SMEM_SZ>>>(gamma, beta, W2, b2, out);
}

// round 13
// speedup vs baseline: 1.0832x; 1.0832x over previous
#include <cuda_runtime.h>

#define NN 512
#define CC 64
#define HH 256
#define EPSF 1e-5f

typedef unsigned long long u64;

// ---------------- packed f32x2 helpers (verified on sm_103a) ----------------
__device__ __forceinline__ u64 pk(float lo, float hi) {
    u64 r; asm("mov.b64 %0,{%1,%2};" : "=l"(r) : "f"(lo), "f"(hi)); return r;
}
__device__ __forceinline__ void unpk(u64 v, float& lo, float& hi) {
    asm("mov.b64 {%0,%1},%2;" : "=f"(lo), "=f"(hi) : "l"(v));
}
__device__ __forceinline__ u64 add2(u64 a, u64 b) {
    u64 r; asm("add.rn.f32x2 %0,%1,%2;" : "=l"(r) : "l"(a), "l"(b)); return r;
}
__device__ __forceinline__ u64 fma2(u64 a, u64 b, u64 c) {
    u64 r; asm("fma.rn.f32x2 %0,%1,%2,%3;" : "=l"(r) : "l"(a), "l"(b), "l"(c)); return r;
}
__device__ __forceinline__ float ex2f(float x) {
    float r; asm("ex2.approx.f32 %0,%1;" : "=f"(r) : "f"(x)); return r;
}
__device__ __forceinline__ float warp_sum(float x) {
#pragma unroll
    for (int off = 16; off > 0; off >>= 1)
        x += __shfl_xor_sync(0xffffffffu, x, off);
    return x;
}

// ---------------- scratch (device globals) ----------------
__device__ float g_T[2][NN][768];
__device__ float g_RA [NN*HH];
__device__ float g_RB [NN*HH];
__device__ float g_A1M[NN*HH];
__device__ float g_A2P[NN*HH];
__device__ float g_B1P[NN*HH];
__device__ float g_B2M[NN*HH];
__device__ float g_SA[NN];
__device__ float g_SB[NN];
__device__ float g_QA[NN];
__device__ float g_QB[NN];
__device__ float g_DA[NN];
__device__ float g_DB[NN];
__device__ float g_CW, g_CWG, g_CWB;

// ---------------------------------------------------------------------------
// Stage 1: GEMM, 32x32 tiles, 128 threads, pipelined k-loop. (R9-proven.)
// ---------------------------------------------------------------------------
__global__ __launch_bounds__(128) void gemm_pre_kernel(
    const float* __restrict__ xl, const float* __restrict__ xr,
    const float* __restrict__ W1)
{
    __shared__ float Xs[64][36];
    __shared__ float Ws[64][36];

    const int z  = blockIdx.z;
    const float* X = z ? xr : xl;
    const int m0 = blockIdx.x * 32;
    const int n0 = blockIdx.y * 32;
    const int sel = n0 >> 8;
    const int h0  = n0 & 255;
    const float* Wbase = W1 + ((2 * sel + z) * 64) * HH + h0;

    const int t = threadIdx.x;
    {
        int f = t & 63, i2 = t >> 6;
#pragma unroll
        for (int ii = 0; ii < 32; ii += 2)
            Xs[f][i2 + ii] = X[(m0 + i2 + ii) * CC + f];
    }
    {
        int n = t & 31, f0 = t >> 5;
#pragma unroll
        for (int ff = 0; ff < 64; ff += 4)
            Ws[f0 + ff][n] = Wbase[(f0 + ff) * HH + n];
    }
    __syncthreads();

    const int tx = t & 7, ty = t >> 3;
    u64 acc[2][2] = {};
    float2 xa = *reinterpret_cast<const float2*>(&Xs[0][2 * ty]);
    ulonglong2 wb = *reinterpret_cast<const ulonglong2*>(&Ws[0][4 * tx]);
#pragma unroll 16
    for (int k = 0; k < 64; k++) {
        const int kn = (k + 1) & 63;
        float2 xan = *reinterpret_cast<const float2*>(&Xs[kn][2 * ty]);
        ulonglong2 wbn = *reinterpret_cast<const ulonglong2*>(&Ws[kn][4 * tx]);
        u64 x0 = pk(xa.x, xa.x), x1 = pk(xa.y, xa.y);
        acc[0][0] = fma2(x0, wb.x, acc[0][0]);
        acc[0][1] = fma2(x0, wb.y, acc[0][1]);
        acc[1][0] = fma2(x1, wb.x, acc[1][0]);
        acc[1][1] = fma2(x1, wb.y, acc[1][1]);
        xa = xan; wb = wbn;
    }
#pragma unroll
    for (int r = 0; r < 2; r++) {
        float a, b, c, d;
        unpk(acc[r][0], a, b);
        unpk(acc[r][1], c, d);
        *reinterpret_cast<float4*>(&g_T[z][m0 + 2 * ty + r][n0 + 4 * tx]) =
            make_float4(a, b, c, d);
    }
}

// ---------------------------------------------------------------------------
// Stage 2: combine shifts + b1 into RA/RB (+masked parts), row stats
// S (sum), Q (sum sq), D (sum w2*gamma*r), and W2 constants.
// ---------------------------------------------------------------------------
__global__ __launch_bounds__(256) void combine_kernel(
    const float* __restrict__ b1, const float* __restrict__ W2,
    const float* __restrict__ gamma, const float* __restrict__ beta)
{
    __shared__ float red[8][6];
    __shared__ float redc[8][3];
    const int i = blockIdx.x, h = threadIdx.x;
    const int lane = h & 31, w = h >> 5;

    float a0  = g_T[0][i][h];
    float a1m = (i > 0)      ? g_T[0][i - 1][256 + h] : 0.f;
    float a2p = (i < NN - 1) ? g_T[0][i + 1][512 + h] : 0.f;
    float ra  = a0 + b1[h] + a1m + a2p;
    g_A1M[i * HH + h] = a1m;
    g_A2P[i * HH + h] = a2p;
    g_RA [i * HH + h] = ra;

    float b0  = g_T[1][i][h];
    float b1p = (i < NN - 1) ? g_T[1][i + 1][256 + h] : 0.f;
    float b2m = (i > 0)      ? g_T[1][i - 1][512 + h] : 0.f;
    float rb  = b0 + b1p + b2m;
    g_B1P[i * HH + h] = b1p;
    g_B2M[i * HH + h] = b2m;
    g_RB [i * HH + h] = rb;

    const float w2h = W2[h];
    const float wg  = w2h * gamma[h];

    float sa = warp_sum(ra);
    float sb = warp_sum(rb);
    float qa = warp_sum(ra * ra);
    float qb = warp_sum(rb * rb);
    float da = warp_sum(wg * ra);
    float db = warp_sum(wg * rb);
    if (lane == 0) {
        red[w][0] = sa; red[w][1] = sb; red[w][2] = qa;
        red[w][3] = qb; red[w][4] = da; red[w][5] = db;
    }
    if (i == 0) {
        float cw  = warp_sum(w2h);
        float cwg = warp_sum(wg);
        float cwb = warp_sum(w2h * beta[h]);
        if (lane == 0) { redc[w][0] = cw; redc[w][1] = cwg; redc[w][2] = cwb; }
    }
    __syncthreads();
    if (h == 0) {
        float v[6] = {};
#pragma unroll
        for (int k = 0; k < 8; k++)
#pragma unroll
            for (int m = 0; m < 6; m++) v[m] += red[k][m];
        g_SA[i] = v[0]; g_SB[i] = v[1];
        g_QA[i] = v[2]; g_QB[i] = v[3];
        g_DA[i] = v[4]; g_DB[i] = v[5];
        if (i == 0) {
            float cw = 0.f, cwg = 0.f, cwb = 0.f;
#pragma unroll
            for (int k = 0; k < 8; k++) {
                cw += redc[k][0]; cwg += redc[k][1]; cwb += redc[k][2];
            }
            g_CW = cw; g_CWG = cwg; g_CWB = cwb;
        }
    }
}

// ---------------------------------------------------------------------------
// Stage 3: fused pair kernel. Blocks 0..511: 16x32 tile, R=2 rows/thread.
//   pass1: cross-dot -> variance (sq = QA + QB + 2X).
//   pass2: nonlinear CELU residual u = 2^m' - ln2*m' (m'=min(h',0));
//          linear part = rs*(DA+DB) + nm*CWG (+ consts).
// Blocks 512..543: border fixup. Main tiles skip border stores.
// ---------------------------------------------------------------------------
#define SA_OFF   0
#define SB_OFF   16384
#define SGB_OFF  50176
#define SW_OFF   52224
#define SSA_OFF  53248
#define SSB_OFF  53312
#define SQA_OFF  53440
#define SQB_OFF  53504
#define SDA_OFF  53632
#define SDB_OFF  53696
#define SMEM_SZ  53824

__global__ __launch_bounds__(256, 4) void pair_fused_kernel(
    const float* __restrict__ gamma, const float* __restrict__ beta,
    const float* __restrict__ W2, const float* __restrict__ b2,
    float* __restrict__ out)
{
    const int t = threadIdx.x;
    const int lane = t & 31, w = t >> 5;

    if (blockIdx.x >= 512) {
        // ================= fixup path =================
        const int fb = blockIdx.x - 512;
#pragma unroll 1
        for (int c = 0; c < 8; c++) {
            const int gw = fb * 8 + w + 256 * c;
            const int side = gw >> 9, pos = gw & 511;
            int i, j;
            if      (side == 0) { i = 0;      j = pos; }
            else if (side == 1) { i = NN - 1; j = pos; }
            else if (side == 2) { i = pos;    j = 0; }
            else                { i = pos;    j = NN - 1; }

            const bool mi0 = (i == 0), mi1 = (i == NN - 1);
            const bool mj0 = (j == 0), mj1 = (j == NN - 1);
            const float4 z4 = make_float4(0.f, 0.f, 0.f, 0.f);

            const float4* RA4 = reinterpret_cast<const float4*>(g_RA)  + i * 64;
            const float4* RB4 = reinterpret_cast<const float4*>(g_RB)  + j * 64;
            const float4* BP4 = reinterpret_cast<const float4*>(g_B1P) + j * 64;
            const float4* BM4 = reinterpret_cast<const float4*>(g_B2M) + j * 64;
            const float4* AP4 = reinterpret_cast<const float4*>(g_A2P) + i * 64;
            const float4* AM4 = reinterpret_cast<const float4*>(g_A1M) + i * 64;

            float s[8], gm[8], bt[8], w2r[8];
#pragma unroll
            for (int half = 0; half < 2; half++) {
                int idx = lane + 32 * half;
                float4 ra = RA4[idx];
                float4 rb = RB4[idx];
                float4 c1 = mi0 ? BP4[idx] : z4;
                float4 c2 = mi1 ? BM4[idx] : z4;
                float4 c3 = mj0 ? AP4[idx] : z4;
                float4 c4 = mj1 ? AM4[idx] : z4;
                int o = 4 * half;
                s[o + 0] = ra.x + rb.x - c1.x - c2.x - c3.x - c4.x;
                s[o + 1] = ra.y + rb.y - c1.y - c2.y - c3.y - c4.y;
                s[o + 2] = ra.z + rb.z - c1.z - c2.z - c3.z - c4.z;
                s[o + 3] = ra.w + rb.w - c1.w - c2.w - c3.w - c4.w;
                float4 gv = reinterpret_cast<const float4*>(gamma)[idx];
                float4 bv = reinterpret_cast<const float4*>(beta )[idx];
                float4 wv = reinterpret_cast<const float4*>(W2   )[idx];
                gm[o] = gv.x; gm[o+1] = gv.y; gm[o+2] = gv.z; gm[o+3] = gv.w;
                bt[o] = bv.x; bt[o+1] = bv.y; bt[o+2] = bv.z; bt[o+3] = bv.w;
                w2r[o] = wv.x; w2r[o+1] = wv.y; w2r[o+2] = wv.z; w2r[o+3] = wv.w;
            }

            float sum = ((s[0] + s[1]) + (s[2] + s[3])) + ((s[4] + s[5]) + (s[6] + s[7]));
            float sq  = fmaf(s[0], s[0], s[1] * s[1]);
            sq = fmaf(s[2], s[2], fmaf(s[3], s[3], sq));
            sq = fmaf(s[4], s[4], sq);
            sq = fmaf(s[5], s[5], sq);
            sq = fmaf(s[6], s[6], fmaf(s[7], s[7], sq));
            sum = warp_sum(sum);
            sq  = warp_sum(sq);

            float mu  = sum * (1.f / 256.f);
            float var = fmaf(sq, 1.f / 256.f, -mu * mu);
            float rs  = rsqrtf(var + EPSF);
            float nm  = -mu * rs;
            float acc = 0.f;
#pragma unroll
            for (int k = 0; k < 8; k++) {
                float hn = fmaf(fmaf(s[k], rs, nm), gm[k], bt[k]);
                float e  = __expf(fminf(hn, 0.f)) - 1.f;
                float v  = fmaxf(hn, 0.f) + e;
                acc = fmaf(v, w2r[k], acc);
            }
            acc = warp_sum(acc);
            if (lane == 0) out[i * NN + j] = acc + b2[0];
        }
        return;
    }

    // ================= main tile path (16 x 32 cells) =================
    extern __shared__ __align__(16) char smem_raw[];
    u64 (*sA)[128] = reinterpret_cast<u64(*)[128]>(smem_raw + SA_OFF);
    u64 (*sB)[33]  = reinterpret_cast<u64(*)[33]>(smem_raw + SB_OFF);
    u64 (*sGB)[2]  = reinterpret_cast<u64(*)[2]>(smem_raw + SGB_OFF);
    u64* sW  = reinterpret_cast<u64*>(smem_raw + SW_OFF);
    float* sSA = reinterpret_cast<float*>(smem_raw + SSA_OFF);
    float* sSB = reinterpret_cast<float*>(smem_raw + SSB_OFF);
    float* sQA = reinterpret_cast<float*>(smem_raw + SQA_OFF);
    float* sQB = reinterpret_cast<float*>(smem_raw + SQB_OFF);
    float* sDA = reinterpret_cast<float*>(smem_raw + SDA_OFF);
    float* sDB = reinterpret_cast<float*>(smem_raw + SDB_OFF);

    const int i0 = (blockIdx.x >> 4) * 16, j0 = (blockIdx.x & 15) * 32;
    const float L2E  = 1.4426950408889634f;
    const float MLN2 = -0.6931471805599453f;

    {   // sA: 16 rows x 128 u64
        const u64* gA = reinterpret_cast<const u64*>(g_RA) + i0 * 128;
#pragma unroll
        for (int k = 0; k < 8; k++) {
            int idx = t + 256 * k;
            sA[idx >> 7][idx & 127] = gA[idx];
        }
    }
    {   // sB transposed: sB[c2][j]
        const u64* gB = reinterpret_cast<const u64*>(g_RB) + j0 * 128;
        int j = t >> 3, part = t & 7;
#pragma unroll
        for (int k = 0; k < 16; k++) {
            int c2 = part + 8 * k;
            sB[c2][j] = gB[j * 128 + c2];
        }
    }
    if (t < 128) {
        float2 gv = reinterpret_cast<const float2*>(gamma)[t];
        float2 bv = reinterpret_cast<const float2*>(beta)[t];
        float2 wv = reinterpret_cast<const float2*>(W2)[t];
        sGB[t][0] = pk(gv.x * L2E, gv.y * L2E);
        sGB[t][1] = pk(bv.x * L2E, bv.y * L2E);
        sW [t]    = pk(wv.x, wv.y);
        if (t < 32) sDB[t] = g_DB[j0 + t];
    } else if (t < 144) {
        sSA[t - 128] = g_SA[i0 + t - 128];
    } else if (t < 176) {
        sSB[t - 144] = g_SB[j0 + t - 144];
    } else if (t < 192) {
        sQA[t - 176] = g_QA[i0 + t - 176];
    } else if (t < 224) {
        sQB[t - 192] = g_QB[j0 + t - 192];
    } else if (t < 240) {
        sDA[t - 224] = g_DA[i0 + t - 224];
    }
    const float CWG  = g_CWG;
    const float CADD = b2[0] - g_CW + g_CWB;
    __syncthreads();

    const int r0 = 2 * w;

    // ---- pass 1: cross-dot X[r] = sum_c RA*RB (packed, pipelined) ----
    u64 xd[2] = {0, 0};
    {
        u64 bv = sB[0][lane];
#pragma unroll 8
        for (int c2 = 0; c2 < 128; c2++) {
            u64 bvn = sB[(c2 + 1) & 127][lane];
            xd[0] = fma2(sA[r0][c2], bv, xd[0]);
            xd[1] = fma2(sA[r0 + 1][c2], bv, xd[1]);
            bv = bvn;
        }
    }
    u64 rs2[2], nm2[2];
    float rsS[2], nmS[2];
#pragma unroll
    for (int r = 0; r < 2; r++) {
        float xl_, xh_; unpk(xd[r], xl_, xh_);
        float sq  = sQA[r0 + r] + sQB[lane] + 2.f * (xl_ + xh_);
        float sum = sSA[r0 + r] + sSB[lane];
        float mu  = sum * (1.f / 256.f);
        float var = fmaf(sq, 1.f / 256.f, -mu * mu);
        float rs  = rsqrtf(var + EPSF);
        float nm  = -mu * rs;
        rsS[r] = rs; nmS[r] = nm;
        rs2[r] = pk(rs, rs);
        nm2[r] = pk(nm, nm);
    }

    // ---- pass 2: CELU residual u = 2^m' - ln2*m', accumulate w2*u ----
    u64 ae[2] = {0, 0};
    {
        u64 bv = sB[0][lane];
        ulonglong2 gb = *reinterpret_cast<const ulonglong2*>(sGB[0]);
        u64 wv = sW[0];
#pragma unroll 4
        for (int c2 = 0; c2 < 128; c2++) {
            const int cn = (c2 + 1) & 127;
            u64 bvn = sB[cn][lane];
            ulonglong2 gbn = *reinterpret_cast<const ulonglong2*>(sGB[cn]);
            u64 wvn = sW[cn];
#pragma unroll
            for (int r = 0; r < 2; r++) {
                u64 s = add2(sA[r0 + r][c2], bv);
                u64 h = fma2(fma2(s, rs2[r], nm2[r]), gb.x, gb.y);
                float hl, hh; unpk(h, hl, hh);
                float ml = fminf(hl, 0.f);
                float mh = fminf(hh, 0.f);
                float ul = fmaf(MLN2, ml, ex2f(ml));
                float uh = fmaf(MLN2, mh, ex2f(mh));
                ae[r] = fma2(pk(ul, uh), wv, ae[r]);
            }
            bv = bvn; gb = gbn; wv = wvn;
        }
    }

    const int gj = j0 + lane;
    const bool jint = (gj != 0) && (gj != NN - 1);
#pragma unroll
    for (int r = 0; r < 2; r++) {
        int gi = i0 + r0 + r;
        if (jint && gi != 0 && gi != NN - 1) {
            float dd = sDA[r0 + r] + sDB[lane];
            float lin = fmaf(rsS[r], dd, nmS[r] * CWG);
            float a, b; unpk(ae[r], a, b);
            out[gi * NN + gj] = lin + (a + b) + CADD;
        }
    }
}

// ---------------------------------------------------------------------------
extern "C" void kernel_launch(void* const* d_in, const int* in_sizes, int n_in,
                              void* d_out, int out_size)
{
    const float* xl    = (const float*)d_in[0];
    const float* xr    = (const float*)d_in[1];
    const float* W1    = (const float*)d_in[2];
    const float* b1    = (const float*)d_in[3];
    const float* gamma = (const float*)d_in[4];
    const float* beta  = (const float*)d_in[5];
    const float* W2    = (const float*)d_in[6];
    const float* b2    = (const float*)d_in[7];
    float* out = (float*)d_out;

    static bool attr_set = false;
    if (!attr_set) {
        cudaFuncSetAttribute(pair_fused_kernel,
                             cudaFuncAttributeMaxDynamicSharedMemorySize, SMEM_SZ);
        attr_set = true;
    }

    dim3 gpre(16, 24, 2);
    gemm_pre_kernel<<<gpre, 128>>>(xl, xr, W1);
    combine_kernel<<<NN, 256>>>(b1, W2, gamma, beta);
    pair_fused_kernel<<<512 + 32, 256, SMEM_SZ>>>(gamma, beta, W2, b2, out);
}